// round 4
// baseline (speedup 1.0000x reference)
#include <cuda_runtime.h>
#include <cstdint>
#include <cstddef>

#define DEV_INLINE __device__ __forceinline__

// ---------------- problem constants ----------------
constexpr int NB = 8, CIN = 512, COUT = 512, RES = 64, WDIM = 512;
constexpr int WP = 66;                 // padded spatial dim
constexpr int PLANE = WP * WP;         // 4356
constexpr int GPT = NB * PLANE;        // 34848 padded pixels total
constexpr int XMARG = 256;             // margin rows each side of g_xpad
constexpr int XROWS = GPT + 2 * XMARG; // 35360

// ---------------- GEMM tiling ----------------
constexpr int BM = 128, BN = 128, KC = 32;
constexpr int NCH = CIN / KC;           // 16 ci-chunks
constexpr int MT = (GPT + BM - 1) / BM; // 273
constexpr int NT = COUT / BN;           // 4
constexpr int NIT = NCH * 9;            // 144 (kc,tap) iterations
constexpr int STRIP_ROWS = BM + 134;    // 262
constexpr int SSTR = 36;                // strip/B row stride in floats

// ---------------- smem layout (bytes) ----------------
constexpr int SO_STRIP = 0;                       // 262*36*4 = 37728
constexpr int SO_B0    = 37760;                   // 128*36*4 = 18432
constexpr int SO_B1    = SO_B0 + 18432;           // 56192
constexpr int SMEM_TOTAL = SO_B1 + 18432;         // 74624 -> 2 CTAs/SM

// ---------------- device scratch (allocation is forbidden) ----------------
__device__ __align__(128) float g_style[NB * CIN];
__device__ __align__(128) float g_xpad[(size_t)XROWS * CIN];  // [row][ci]
__device__ __align__(128) float g_wtap[9 * COUT * CIN];       // [tap][co][ci]

// ---------------- PTX helpers (sm_80 baseline only) ----------------
DEV_INLINE uint32_t smem_u32(const void* p) {
    uint32_t a;
    asm("{ .reg .u64 t; cvta.to.shared.u64 t, %1; cvt.u32.u64 %0, t; }"
        : "=r"(a) : "l"(p));
    return a;
}

DEV_INLINE float tf32_rna(float v) {
    uint32_t t;
    asm("cvt.rna.tf32.f32 %0, %1;" : "=r"(t) : "f"(v));
    return __uint_as_float(t);
}

DEV_INLINE void cp_async16(uint32_t dst, const void* src) {
    asm volatile("cp.async.ca.shared.global [%0], [%1], 16;"
                 :: "r"(dst), "l"(src) : "memory");
}
DEV_INLINE void cp_commit() {
    asm volatile("cp.async.commit_group;" ::: "memory");
}
DEV_INLINE void cp_wait_all() {
    asm volatile("cp.async.wait_group 0;" ::: "memory");
}

DEV_INLINE void mma_tf32(float* c, const uint32_t* a, const uint32_t* b) {
    asm volatile(
        "mma.sync.aligned.m16n8k8.row.col.f32.tf32.tf32.f32 "
        "{%0,%1,%2,%3}, {%4,%5,%6,%7}, {%8,%9}, {%0,%1,%2,%3};"
        : "+f"(c[0]), "+f"(c[1]), "+f"(c[2]), "+f"(c[3])
        : "r"(a[0]), "r"(a[1]), "r"(a[2]), "r"(a[3]),
          "r"(b[0]), "r"(b[1]));
}

// ============================================================================
// Kernel 1: style[b][ci] = w[b,:] . affine_w[ci,:] + affine_b[ci]
// ============================================================================
__global__ void k_style(const float* __restrict__ w,
                        const float* __restrict__ aw,
                        const float* __restrict__ ab) {
    int gw = (blockIdx.x * blockDim.x + threadIdx.x) >> 5;
    int lane = threadIdx.x & 31;
    if (gw >= NB * CIN) return;
    int b = gw >> 9;
    int ci = gw & (CIN - 1);
    const float* wr = w + b * WDIM;
    const float* ar = aw + ci * WDIM;
    float s = 0.f;
    for (int d = lane; d < WDIM; d += 32) s += wr[d] * ar[d];
    #pragma unroll
    for (int o = 16; o; o >>= 1) s += __shfl_xor_sync(0xFFFFFFFFu, s, o);
    if (lane == 0) g_style[b * CIN + ci] = s + ab[ci];
}

// ============================================================================
// Kernel 2: g_wtap[tap][co][ci] = tf32(weight[co][ci][tap])
// ============================================================================
__global__ void k_wprep(const float* __restrict__ wt) {
    int idx = blockIdx.x * 256 + threadIdx.x;   // co*CIN + ci
    if (idx >= COUT * CIN) return;
    const float* src = wt + (size_t)idx * 9;
    #pragma unroll
    for (int tp = 0; tp < 9; tp++)
        g_wtap[tp * (COUT * CIN) + idx] = tf32_rna(src[tp]);
}

// ============================================================================
// Kernel 3: zero margins + zero-padding borders of g_xpad
// ============================================================================
__global__ void k_zero() {
    int row = (int)blockIdx.x - XMARG;
    bool z;
    if (row < 0 || row >= GPT) z = true;
    else {
        int rem = row % PLANE;
        int py = rem / WP, px = rem % WP;
        z = (py == 0) || (py == WP - 1) || (px == 0) || (px == WP - 1);
    }
    if (!z) return;
    float4* dst = (float4*)(g_xpad + (size_t)(row + XMARG) * CIN);
    dst[threadIdx.x] = make_float4(0.f, 0.f, 0.f, 0.f);
}

// ============================================================================
// Kernel 4: g_xpad[gp][ci] = tf32( x[b,ci,py-1,px-1] * style[b,ci] )
// ============================================================================
__global__ void k_xprep(const float* __restrict__ x) {
    __shared__ float tile[32 * 65];
    __shared__ float sstyle[32];
    int cib = blockIdx.x * 32;
    int py  = blockIdx.y + 1;          // padded row 1..64
    int b   = blockIdx.z;
    int t   = threadIdx.x;
    if (t < 32) sstyle[t] = g_style[b * CIN + cib + t];
    int i = t >> 3, j = t & 7;
    const float* srow = x + (((size_t)(b * CIN + cib + i) * RES + (py - 1)) * RES);
    float4 v0 = ((const float4*)srow)[j * 2];
    float4 v1 = ((const float4*)srow)[j * 2 + 1];
    int c = j * 8;
    tile[i * 65 + c + 0] = v0.x; tile[i * 65 + c + 1] = v0.y;
    tile[i * 65 + c + 2] = v0.z; tile[i * 65 + c + 3] = v0.w;
    tile[i * 65 + c + 4] = v1.x; tile[i * 65 + c + 5] = v1.y;
    tile[i * 65 + c + 6] = v1.z; tile[i * 65 + c + 7] = v1.w;
    __syncthreads();
    int wrp = t >> 5, l = t & 31;
    float st = sstyle[l];
    size_t rowbase = (size_t)XMARG + (size_t)b * PLANE + (size_t)py * WP;
    #pragma unroll
    for (int pp = 0; pp < 8; pp++) {
        int px = wrp * 8 + pp;
        float v = tile[l * 65 + px] * st;
        g_xpad[(rowbase + px + 1) * CIN + cib + l] = tf32_rna(v);
    }
}

// ============================================================================
// Kernel 5: implicit-GEMM conv, mma.sync tf32 (sm_80-level), cp.async pipeline
// grid (NT=4, MT=273), 256 threads, 2 CTAs/SM
// ============================================================================
__global__ __launch_bounds__(256, 2) void k_gemm(const float* __restrict__ bias,
                                                 float* __restrict__ out) {
    extern __shared__ __align__(128) char smem[];
    const int t = threadIdx.x;
    const int wid = t >> 5;
    const int lane = t & 31;
    const int g = lane >> 2;          // 0..7
    const int tg = lane & 3;          // 0..3
    const int wm = wid >> 2;          // 0..1  (m warp coord, 64 rows each)
    const int wn = wid & 3;           // 0..3  (n warp coord, 32 cols each)
    const int n0 = blockIdx.x * BN;
    const int gp0 = (int)blockIdx.y * BM;

    uint32_t sbase = smem_u32(smem);
    float* stripf = (float*)(smem + SO_STRIP);

    // ---- accumulators: 4 mfrags x 4 nfrags x 4 ----
    float c[4][4][4];
    #pragma unroll
    for (int mi = 0; mi < 4; mi++)
        #pragma unroll
        for (int ni = 0; ni < 4; ni++)
            #pragma unroll
            for (int q = 0; q < 4; q++) c[mi][ni][q] = 0.f;

    const float* xsrc = g_xpad + (size_t)(XMARG + gp0 - 67) * CIN;

    // per-thread frag base offsets (in floats)
    const int a_off = (wm * 64 + g) * SSTR + tg;
    const int b_off = (wn * 32 + g) * SSTR + tg;

    // ---- issue B(0) ----
    {
        const float* wsrc = g_wtap + (size_t)n0 * CIN;   // tap0, kc0
        #pragma unroll
        for (int k = 0; k < 4; k++) {
            int idx = t + k * 256;
            int r = idx >> 3, j = idx & 7;
            cp_async16(sbase + SO_B0 + (r * SSTR + j * 4) * 4,
                       wsrc + (size_t)r * CIN + j * 4);
        }
        cp_commit();
    }

    for (int it = 0; it < NIT; it++) {
        const int kc = it / 9;
        const int tap = it - kc * 9;

        if (tap == 0) {
            __syncthreads();   // previous chunk's strip users done
            const float* src = xsrc + kc * KC;
            #pragma unroll
            for (int k = 0; k < 9; k++) {
                int idx = t + k * 256;
                if (idx < STRIP_ROWS * 8) {
                    int r = idx >> 3, j = idx & 7;
                    cp_async16(sbase + SO_STRIP + (r * SSTR + j * 4) * 4,
                               src + (size_t)r * CIN + j * 4);
                }
            }
            cp_commit();
        }

        cp_wait_all();
        __syncthreads();       // B(it) + strip visible; prev compute done

        // prefetch B(it+1) into the other buffer
        if (it + 1 < NIT) {
            int kc2 = (it + 1) / 9;
            int tap2 = (it + 1) - kc2 * 9;
            const float* wsrc =
                g_wtap + ((size_t)tap2 * COUT + n0) * CIN + kc2 * KC;
            uint32_t bdst = sbase + (((it + 1) & 1) ? SO_B1 : SO_B0);
            #pragma unroll
            for (int k = 0; k < 4; k++) {
                int idx = t + k * 256;
                int r = idx >> 3, j = idx & 7;
                cp_async16(bdst + (r * SSTR + j * 4) * 4,
                           wsrc + (size_t)r * CIN + j * 4);
            }
            cp_commit();
        }

        // ---- compute: tap shift is a pure strip-row offset ----
        const int srow0 = (tap / 3) * WP + (tap % 3);
        const uint32_t* ab =
            (const uint32_t*)(stripf + srow0 * SSTR + a_off);
        const uint32_t* bb =
            (const uint32_t*)(smem + ((it & 1) ? SO_B1 : SO_B0)) + b_off;

        #pragma unroll
        for (int ks = 0; ks < 4; ks++) {
            uint32_t A[4][4];
            #pragma unroll
            for (int mi = 0; mi < 4; mi++) {
                const uint32_t* ap = ab + mi * (16 * SSTR) + ks * 8;
                A[mi][0] = ap[0];
                A[mi][1] = ap[8 * SSTR];
                A[mi][2] = ap[4];
                A[mi][3] = ap[8 * SSTR + 4];
            }
            uint32_t B[4][2];
            #pragma unroll
            for (int ni = 0; ni < 4; ni++) {
                const uint32_t* bp = bb + ni * (8 * SSTR) + ks * 8;
                B[ni][0] = bp[0];
                B[ni][1] = bp[4];
            }
            #pragma unroll
            for (int mi = 0; mi < 4; mi++)
                #pragma unroll
                for (int ni = 0; ni < 4; ni++)
                    mma_tf32(c[mi][ni], A[mi], B[ni]);
        }
    }

    // ---- epilogue: c[mi][ni] rows (g, g+8), cols (2tg, 2tg+1) ----
    #pragma unroll
    for (int mi = 0; mi < 4; mi++) {
        #pragma unroll
        for (int half = 0; half < 2; half++) {
            int mloc = wm * 64 + mi * 16 + half * 8 + g;
            int gp = gp0 + mloc;
            if (gp >= GPT) continue;
            int b = gp / PLANE;
            int rem = gp - b * PLANE;
            int py = rem / WP, px = rem - py * WP;
            if (py < 1 || py > RES || px < 1 || px > RES) continue;
            size_t obase =
                (((size_t)b * COUT) * RES + (py - 1)) * RES + (px - 1);
            #pragma unroll
            for (int ni = 0; ni < 4; ni++) {
                #pragma unroll
                for (int j = 0; j < 2; j++) {
                    int co = n0 + wn * 32 + ni * 8 + 2 * tg + j;
                    out[obase + (size_t)co * (RES * RES)] =
                        c[mi][ni][half * 2 + j] + __ldg(&bias[co]);
                }
            }
        }
    }
}

// ============================================================================
// launch
// ============================================================================
extern "C" void kernel_launch(void* const* d_in, const int* in_sizes, int n_in,
                              void* d_out, int out_size) {
    const float* x   = (const float*)d_in[0];
    const float* w   = (const float*)d_in[1];
    const float* wt  = (const float*)d_in[2];
    const float* bia = (const float*)d_in[3];
    const float* aw  = (const float*)d_in[4];
    const float* ab  = (const float*)d_in[5];
    float* out = (float*)d_out;

    cudaFuncSetAttribute(k_gemm, cudaFuncAttributeMaxDynamicSharedMemorySize,
                         SMEM_TOTAL);

    k_style<<<(NB * CIN * 32 + 255) / 256, 256>>>(w, aw, ab);
    k_wprep<<<(COUT * CIN + 255) / 256, 256>>>(wt);
    k_zero<<<XROWS, 128>>>();
    k_xprep<<<dim3(CIN / 32, RES, NB), 256>>>(x);
    k_gemm<<<dim3(NT, MT), 256, SMEM_TOTAL>>>(bia, out);
}